// round 1
// baseline (speedup 1.0000x reference)
#include <cuda_runtime.h>
#include <math.h>

#define BN 16
#define LL 1024
#define TOK (BN*LL)          // 16384 tokens
#define DM 256
#define DI 512
#define DS 16
#define DTR 16
#define NPROJ 48             // DTR + 2*DS

// ---------------- scratch (device globals; no allocation allowed) ------------
__device__ float g_h[TOK*DM];        // residual stream (b, l, m)
__device__ float g_xn[TOK*DM];       // layernormed
__device__ float g_xz[TOK*2*DI];     // in_proj output: [0:DI)=xin, [DI:2DI)=z
__device__ float g_u[TOK*DI];        // conv+silu output (u)
__device__ float g_proj[TOK*NPROJ];  // x_proj output: dt | B | C
__device__ float g_delta[TOK*DI];    // softplus(dt @ dtw + dtb)
__device__ float g_y[TOK*DI];        // scan output * silu(z)

// ---------------- helpers ----------------------------------------------------
__device__ __forceinline__ float sigmoidf_(float x) {
    return 1.f / (1.f + __expf(-x));
}
__device__ __forceinline__ float softplusf_(float x) {
    return (x > 20.f) ? x : log1pf(__expf(x));
}

// block reduce over 256 threads (8 warps). sred must be >= 8 floats shared.
__device__ __forceinline__ float block_sum_256(float v, float* sred, int m) {
    #pragma unroll
    for (int o = 16; o; o >>= 1) v += __shfl_xor_sync(0xffffffffu, v, o);
    if ((m & 31) == 0) sred[m >> 5] = v;
    __syncthreads();
    if (m == 0) {
        float tot = 0.f;
        #pragma unroll
        for (int i = 0; i < 8; i++) tot += sred[i];
        sred[0] = tot;
    }
    __syncthreads();
    float tot = sred[0];
    __syncthreads();   // safe reuse of sred
    return tot;
}

// ---------------- stem conv (k=3, pad=1) + relu ------------------------------
__global__ void stem_kernel(const float* __restrict__ x,
                            const float* __restrict__ sw,
                            const float* __restrict__ sb) {
    int t = blockIdx.x;              // token
    int m = threadIdx.x;             // out channel
    int b = t / LL, l = t % LL;
    __shared__ float xs[3][3];       // [c][k] = x[b][c][l-1+k]
    if (m < 9) {
        int c = m / 3, k = m % 3;
        int ll = l - 1 + k;
        xs[c][k] = (ll >= 0 && ll < LL) ? x[(b*3 + c)*LL + ll] : 0.f;
    }
    __syncthreads();
    float acc = sb[m];
    #pragma unroll
    for (int c = 0; c < 3; c++)
        #pragma unroll
        for (int k = 0; k < 3; k++)
            acc = fmaf(xs[c][k], sw[(m*3 + c)*3 + k], acc);
    g_h[t*DM + m] = fmaxf(acc, 0.f);
}

// ---------------- layernorm over DM=256 --------------------------------------
__global__ void ln_kernel(const float* __restrict__ in,
                          const float* __restrict__ g,
                          const float* __restrict__ b,
                          float* __restrict__ out) {
    __shared__ float sred[8];
    int t = blockIdx.x, m = threadIdx.x;
    float v = in[t*DM + m];
    float mean = block_sum_256(v, sred, m) * (1.f / DM);
    float d = v - mean;
    float var = block_sum_256(d*d, sred, m) * (1.f / DM);
    float rstd = rsqrtf(var + 1e-5f);
    out[t*DM + m] = d * rstd * g[m] + b[m];
}

// ---------------- SGEMM: C[M,N] = A[M,K] @ W[N,K]^T, with epilogue -----------
// EPI 0: C = acc ; EPI 1: C = softplus(acc + bias[n]) ; EPI 2: C += acc
#define TM 128
#define TN 128
#define TK 8
template<int EPI>
__global__ __launch_bounds__(256) void sgemm_kernel(
        const float* __restrict__ A, int lda,
        const float* __restrict__ W,     // N x K row-major
        float* __restrict__ C, int ldc,
        const float* __restrict__ bias,
        int M, int N, int K) {
    __shared__ float As[TK][TM];
    __shared__ float Ws[TK][TN];
    int bm = blockIdx.y * TM;
    int bn = blockIdx.x * TN;
    int tid = threadIdx.x;
    int tr = tid / 16, tc = tid % 16;      // 16x16 thread grid, 8x8 per thread

    float acc[8][8];
    #pragma unroll
    for (int i = 0; i < 8; i++)
        #pragma unroll
        for (int j = 0; j < 8; j++) acc[i][j] = 0.f;

    for (int k0 = 0; k0 < K; k0 += TK) {
        {   // load A tile 128x8 (transposed into As[k][m]) — float4 per thread
            int row = tid >> 1, seg = (tid & 1) * 4;
            int gm = bm + row;
            float4 v = make_float4(0.f, 0.f, 0.f, 0.f);
            if (gm < M)
                v = *reinterpret_cast<const float4*>(A + (size_t)gm*lda + k0 + seg);
            As[seg+0][row] = v.x; As[seg+1][row] = v.y;
            As[seg+2][row] = v.z; As[seg+3][row] = v.w;
        }
        {   // load W tile 128x8 (transposed into Ws[k][n])
            int row = tid >> 1, seg = (tid & 1) * 4;
            int gn = bn + row;
            float4 v = make_float4(0.f, 0.f, 0.f, 0.f);
            if (gn < N)
                v = *reinterpret_cast<const float4*>(W + (size_t)gn*K + k0 + seg);
            Ws[seg+0][row] = v.x; Ws[seg+1][row] = v.y;
            Ws[seg+2][row] = v.z; Ws[seg+3][row] = v.w;
        }
        __syncthreads();
        #pragma unroll
        for (int kk = 0; kk < TK; kk++) {
            float a[8], bfr[8];
            *reinterpret_cast<float4*>(&a[0])   = *reinterpret_cast<float4*>(&As[kk][tr*8]);
            *reinterpret_cast<float4*>(&a[4])   = *reinterpret_cast<float4*>(&As[kk][tr*8+4]);
            *reinterpret_cast<float4*>(&bfr[0]) = *reinterpret_cast<float4*>(&Ws[kk][tc*8]);
            *reinterpret_cast<float4*>(&bfr[4]) = *reinterpret_cast<float4*>(&Ws[kk][tc*8+4]);
            #pragma unroll
            for (int i = 0; i < 8; i++)
                #pragma unroll
                for (int j = 0; j < 8; j++)
                    acc[i][j] = fmaf(a[i], bfr[j], acc[i][j]);
        }
        __syncthreads();
    }

    #pragma unroll
    for (int i = 0; i < 8; i++) {
        int gm = bm + tr*8 + i;
        if (gm >= M) continue;
        #pragma unroll
        for (int j = 0; j < 8; j++) {
            int gn = bn + tc*8 + j;
            if (gn >= N) continue;
            float v = acc[i][j];
            if (EPI == 1) v = softplusf_(v + bias[gn]);
            if (EPI == 2) v += C[(size_t)gm*ldc + gn];
            C[(size_t)gm*ldc + gn] = v;
        }
    }
}

// ---------------- causal depthwise conv (k=4, left pad 3) + silu -------------
__global__ void conv_silu_kernel(const float* __restrict__ cw,
                                 const float* __restrict__ cb) {
    int idx = blockIdx.x * blockDim.x + threadIdx.x;
    if (idx >= TOK*DI) return;
    int d = idx % DI;
    int t = idx / DI;
    int l = t % LL;
    float acc = cb[d];
    #pragma unroll
    for (int k = 0; k < 4; k++) {
        int ls = l - 3 + k;
        if (ls >= 0)
            acc = fmaf(g_xz[(size_t)(t - 3 + k)*(2*DI) + d], cw[d*4 + k], acc);
    }
    g_u[idx] = acc * sigmoidf_(acc);
}

// ---------------- selective scan (sequential over L) + gate ------------------
#define SCH 8
__global__ __launch_bounds__(128) void scan_kernel(const float* __restrict__ Alog,
                                                   const float* __restrict__ Dp) {
    int b = blockIdx.y;
    int d = blockIdx.x * 128 + threadIdx.x;
    int tid = threadIdx.x;

    float A[DS], h[DS];
    #pragma unroll
    for (int s = 0; s < DS; s++) {
        A[s] = -__expf(Alog[d*DS + s]);
        h[s] = 0.f;
    }
    float Dd = Dp[d];

    __shared__ float sB[SCH][DS];
    __shared__ float sC[SCH][DS];
    int t0 = b * LL;

    for (int l0 = 0; l0 < LL; l0 += SCH) {
        // cooperatively load B_t / C_t for SCH steps (256 floats / 128 threads)
        #pragma unroll
        for (int r = 0; r < 2; r++) {
            int i = tid + r*128;
            int step = i / (2*DS);
            int j = i % (2*DS);
            float val = g_proj[(size_t)(t0 + l0 + step)*NPROJ + DTR + j];
            if (j < DS) sB[step][j] = val;
            else        sC[step][j - DS] = val;
        }
        __syncthreads();

        float dc[SCH], uc[SCH], zc[SCH];
        #pragma unroll
        for (int i = 0; i < SCH; i++) {
            size_t t = (size_t)(t0 + l0 + i);
            dc[i] = g_delta[t*DI + d];
            uc[i] = g_u[t*DI + d];
            zc[i] = g_xz[t*2*DI + DI + d];
        }
        #pragma unroll
        for (int i = 0; i < SCH; i++) {
            float dlt = dc[i], uu = uc[i];
            float du = dlt * uu;
            float y = 0.f;
            #pragma unroll
            for (int s = 0; s < DS; s++) {
                float ep = __expf(dlt * A[s]);
                h[s] = fmaf(h[s], ep, du * sB[i][s]);
                y = fmaf(h[s], sC[i][s], y);
            }
            y = fmaf(uu, Dd, y);
            float zz = zc[i];
            y *= zz * sigmoidf_(-(-zz)); // silu(z) = z*sigmoid(z)
            g_y[(size_t)(t0 + l0 + i)*DI + d] = y;
        }
        __syncthreads();
    }
}

// ---------------- final LN + head projection + sigmoid -----------------------
__global__ void head_kernel(const float* __restrict__ g,
                            const float* __restrict__ b,
                            const float* __restrict__ hw,
                            const float* __restrict__ hb,
                            float* __restrict__ out) {
    __shared__ float sred[8];
    int t = blockIdx.x, m = threadIdx.x;
    float v = g_h[t*DM + m];
    float mean = block_sum_256(v, sred, m) * (1.f / DM);
    float d = v - mean;
    float var = block_sum_256(d*d, sred, m) * (1.f / DM);
    float rstd = rsqrtf(var + 1e-5f);
    float hn = d * rstd * g[m] + b[m];
    float tot = block_sum_256(hn * hw[m], sred, m);
    if (m == 0) out[t] = sigmoidf_(tot + hb[0]);
}

// ---------------- host launcher ----------------------------------------------
extern "C" void kernel_launch(void* const* d_in, const int* in_sizes, int n_in,
                              void* d_out, int out_size) {
    const float* x       = (const float*)d_in[0];
    const float* stem_w  = (const float*)d_in[1];
    const float* stem_b  = (const float*)d_in[2];
    const float* norm_g  = (const float*)d_in[3];
    const float* norm_b  = (const float*)d_in[4];
    const float* in_w    = (const float*)d_in[5];
    const float* conv_w  = (const float*)d_in[6];
    const float* conv_b  = (const float*)d_in[7];
    const float* xpw     = (const float*)d_in[8];
    const float* dtw     = (const float*)d_in[9];
    const float* dtb     = (const float*)d_in[10];
    const float* A_log   = (const float*)d_in[11];
    const float* Dp      = (const float*)d_in[12];
    const float* out_w   = (const float*)d_in[13];
    const float* fn_g    = (const float*)d_in[14];
    const float* fn_b    = (const float*)d_in[15];
    const float* head_w  = (const float*)d_in[16];
    const float* head_b  = (const float*)d_in[17];
    float* out = (float*)d_out;

    float *p_h, *p_xn, *p_xz, *p_u, *p_proj, *p_delta, *p_y;
    cudaGetSymbolAddress((void**)&p_h,     g_h);
    cudaGetSymbolAddress((void**)&p_xn,    g_xn);
    cudaGetSymbolAddress((void**)&p_xz,    g_xz);
    cudaGetSymbolAddress((void**)&p_u,     g_u);
    cudaGetSymbolAddress((void**)&p_proj,  g_proj);
    cudaGetSymbolAddress((void**)&p_delta, g_delta);
    cudaGetSymbolAddress((void**)&p_y,     g_y);

    stem_kernel<<<TOK, 256>>>(x, stem_w, stem_b);

    for (int i = 0; i < 4; i++) {
        ln_kernel<<<TOK, 256>>>(p_h, norm_g + i*DM, norm_b + i*DM, p_xn);

        // in_proj: [TOK,2*DI] = xn[TOK,DM] @ W[2*DI,DM]^T
        {
            dim3 grid((2*DI + TN - 1)/TN, (TOK + TM - 1)/TM);
            sgemm_kernel<0><<<grid, 256>>>(p_xn, DM, in_w + (size_t)i*2*DI*DM,
                                           p_xz, 2*DI, nullptr, TOK, 2*DI, DM);
        }

        conv_silu_kernel<<<(TOK*DI + 255)/256, 256>>>(conv_w + (size_t)i*DI*4,
                                                      conv_b + (size_t)i*DI);

        // x_proj: [TOK,48] = u[TOK,DI] @ xw[48,DI]^T
        {
            dim3 grid((NPROJ + TN - 1)/TN, (TOK + TM - 1)/TM);
            sgemm_kernel<0><<<grid, 256>>>(p_u, DI, xpw + (size_t)i*NPROJ*DI,
                                           p_proj, NPROJ, nullptr, TOK, NPROJ, DI);
        }

        // delta: softplus(dt[TOK,16] @ dtw[DI,16]^T + dtb)
        {
            dim3 grid((DI + TN - 1)/TN, (TOK + TM - 1)/TM);
            sgemm_kernel<1><<<grid, 256>>>(p_proj, NPROJ, dtw + (size_t)i*DI*DTR,
                                           p_delta, DI, dtb + (size_t)i*DI,
                                           TOK, DI, DTR);
        }

        // scan + gate
        {
            dim3 grid(DI/128, BN);
            scan_kernel<<<grid, 128>>>(A_log + (size_t)i*DI*DS, Dp + (size_t)i*DI);
        }

        // out proj + residual: h += y[TOK,DI] @ ow[DM,DI]^T
        {
            dim3 grid((DM + TN - 1)/TN, (TOK + TM - 1)/TM);
            sgemm_kernel<2><<<grid, 256>>>(p_y, DI, out_w + (size_t)i*DM*DI,
                                           p_h, DM, nullptr, TOK, DM, DI);
        }
    }

    head_kernel<<<TOK, 256>>>(fn_g, fn_b, head_w, head_b, out);
    (void)in_sizes; (void)n_in; (void)out_size;
}

// round 4
// speedup vs baseline: 1.4412x; 1.4412x over previous
#include <cuda_runtime.h>
#include <math.h>
#include <cstdint>

#define BN 16
#define LL 1024
#define TOK (BN*LL)          // 16384 tokens
#define DM 256
#define DI 512
#define DS 16
#define DTR 16
#define NPROJ 48             // DTR + 2*DS

// ---------------- scratch (device globals; no allocation allowed) ------------
__device__ float g_h[TOK*DM];        // residual stream (b, l, m)
__device__ float g_xn[TOK*DM];       // layernormed
__device__ float g_xz[TOK*2*DI];     // in_proj output: [0:DI)=xin, [DI:2DI)=z
__device__ float g_u[TOK*DI];        // conv+silu output (u)
__device__ float g_proj[TOK*NPROJ];  // x_proj output: dt | B | C
__device__ float g_delta[TOK*DI];    // softplus(dt @ dtw + dtb)
__device__ float g_y[TOK*DI];        // scan output * silu(z)

// ---------------- helpers ----------------------------------------------------
__device__ __forceinline__ float sigmoidf_(float x) {
    return 1.f / (1.f + __expf(-x));
}
__device__ __forceinline__ float softplusf_(float x) {
    return (x > 20.f) ? x : log1pf(__expf(x));
}
__device__ __forceinline__ uint32_t tf32r_(float f) {
    uint32_t u;
    asm("cvt.rna.tf32.f32 %0, %1;" : "=r"(u) : "f"(f));
    return u;
}
__device__ __forceinline__ void mma_tf32_(float* c, const uint32_t* a, const uint32_t* b) {
    asm volatile(
        "mma.sync.aligned.m16n8k8.row.col.f32.tf32.tf32.f32 "
        "{%0,%1,%2,%3}, {%4,%5,%6,%7}, {%8,%9}, {%0,%1,%2,%3};"
        : "+f"(c[0]), "+f"(c[1]), "+f"(c[2]), "+f"(c[3])
        : "r"(a[0]), "r"(a[1]), "r"(a[2]), "r"(a[3]), "r"(b[0]), "r"(b[1]));
}

// ---------------- tensor-core tf32 GEMM: C[M,N] = A[M,K] @ W[N,K]^T ----------
// CTA tile 128x128, BK=32, double-buffered swizzled SMEM, warp tile 64x32.
// EPI 0: C = acc ; EPI 2: C += acc
#define GBM 128
#define GBN 128
#define GBK 32
#define TILE_U32 (GBM*GBK)       // 4096 u32 per tile
#define STAGE_U32 (2*TILE_U32)   // A + W
#define GEMM_SMEM (2*STAGE_U32*4)  // 64 KB

// swizzled float offset within a 128x32 tile
__device__ __forceinline__ int sofs_(int row, int k) {
    return row * 32 + ((((k >> 2) ^ row) & 7) << 2) + (k & 3);
}

__device__ __forceinline__ void tile_ldg_(const float* __restrict__ G, int ld,
                                          int row0, int k0, int tid, float4* r) {
    #pragma unroll
    for (int i = 0; i < 4; i++) {
        int row = i * 32 + (tid >> 3);
        int c4 = tid & 7;
        r[i] = *reinterpret_cast<const float4*>(G + (size_t)(row0 + row) * ld + k0 + c4 * 4);
    }
}
__device__ __forceinline__ void tile_sts_(const float4* r, uint32_t* S, int tid) {
    #pragma unroll
    for (int i = 0; i < 4; i++) {
        int row = i * 32 + (tid >> 3);
        int c4 = tid & 7;
        int sc4 = c4 ^ (row & 7);
        uint4 u;
        u.x = tf32r_(r[i].x); u.y = tf32r_(r[i].y);
        u.z = tf32r_(r[i].z); u.w = tf32r_(r[i].w);
        *reinterpret_cast<uint4*>(S + row * 32 + sc4 * 4) = u;
    }
}

template<int EPI>
__global__ __launch_bounds__(256) void mma_gemm_kernel(
        const float* __restrict__ A, int lda,
        const float* __restrict__ W,
        float* __restrict__ C, int ldc,
        int K) {
    extern __shared__ uint32_t smem_u[];
    int tid = threadIdx.x;
    int wid = tid >> 5, lane = tid & 31;
    int g = lane >> 2, tg = lane & 3;
    int bm = blockIdx.y * GBM;
    int bn = blockIdx.x * GBN;
    int wm0 = (wid & 1) * 64;        // warp row offset in tile
    int wn0 = (wid >> 1) * 32;       // warp col offset in tile

    float acc[4][4][4];
    #pragma unroll
    for (int mf = 0; mf < 4; mf++)
        #pragma unroll
        for (int nf = 0; nf < 4; nf++)
            #pragma unroll
            for (int r = 0; r < 4; r++) acc[mf][nf][r] = 0.f;

    const int nst = K / GBK;

    // prologue: stage 0
    {
        float4 ra[4], rw[4];
        tile_ldg_(A, lda, bm, 0, tid, ra);
        tile_ldg_(W, K,   bn, 0, tid, rw);
        tile_sts_(ra, smem_u, tid);
        tile_sts_(rw, smem_u + TILE_U32, tid);
    }
    __syncthreads();

    for (int s = 0; s < nst; s++) {
        float4 ra[4], rw[4];
        if (s + 1 < nst) {
            int k0 = (s + 1) * GBK;
            tile_ldg_(A, lda, bm, k0, tid, ra);
            tile_ldg_(W, K,   bn, k0, tid, rw);
        }
        const uint32_t* As = smem_u + (s & 1) * STAGE_U32;
        const uint32_t* Ws = As + TILE_U32;

        #pragma unroll
        for (int kk = 0; kk < 4; kk++) {
            int k0 = kk * 8;
            uint32_t afr[4][4], bfr[4][2];
            #pragma unroll
            for (int mf = 0; mf < 4; mf++) {
                int r0 = wm0 + mf * 16;
                afr[mf][0] = As[sofs_(r0 + g,     k0 + tg)];
                afr[mf][1] = As[sofs_(r0 + g + 8, k0 + tg)];
                afr[mf][2] = As[sofs_(r0 + g,     k0 + tg + 4)];
                afr[mf][3] = As[sofs_(r0 + g + 8, k0 + tg + 4)];
            }
            #pragma unroll
            for (int nf = 0; nf < 4; nf++) {
                int r0 = wn0 + nf * 8;
                bfr[nf][0] = Ws[sofs_(r0 + g, k0 + tg)];
                bfr[nf][1] = Ws[sofs_(r0 + g, k0 + tg + 4)];
            }
            #pragma unroll
            for (int mf = 0; mf < 4; mf++)
                #pragma unroll
                for (int nf = 0; nf < 4; nf++)
                    mma_tf32_(acc[mf][nf], afr[mf], bfr[nf]);
        }

        if (s + 1 < nst) {
            uint32_t* nb = smem_u + ((s + 1) & 1) * STAGE_U32;
            tile_sts_(ra, nb, tid);
            tile_sts_(rw, nb + TILE_U32, tid);
        }
        __syncthreads();
    }

    // epilogue
    #pragma unroll
    for (int mf = 0; mf < 4; mf++) {
        int gr = bm + wm0 + mf * 16 + g;
        #pragma unroll
        for (int nf = 0; nf < 4; nf++) {
            int gc = bn + wn0 + nf * 8 + 2 * tg;
            float2 v01 = make_float2(acc[mf][nf][0], acc[mf][nf][1]);
            float2 v23 = make_float2(acc[mf][nf][2], acc[mf][nf][3]);
            float* p0 = C + (size_t)gr * ldc + gc;
            float* p1 = C + (size_t)(gr + 8) * ldc + gc;
            if (EPI == 2) {
                float2 o0 = *reinterpret_cast<float2*>(p0);
                float2 o1 = *reinterpret_cast<float2*>(p1);
                v01.x += o0.x; v01.y += o0.y;
                v23.x += o1.x; v23.y += o1.y;
            }
            *reinterpret_cast<float2*>(p0) = v01;
            *reinterpret_cast<float2*>(p1) = v23;
        }
    }
}

__device__ __forceinline__ float block_sum_256(float v, float* sred, int m) {
    #pragma unroll
    for (int o = 16; o; o >>= 1) v += __shfl_xor_sync(0xffffffffu, v, o);
    if ((m & 31) == 0) sred[m >> 5] = v;
    __syncthreads();
    if (m == 0) {
        float tot = 0.f;
        #pragma unroll
        for (int i = 0; i < 8; i++) tot += sred[i];
        sred[0] = tot;
    }
    __syncthreads();
    float tot = sred[0];
    __syncthreads();
    return tot;
}

// ---------------- stem conv (k=3, pad=1) + relu ------------------------------
__global__ void stem_kernel(const float* __restrict__ x,
                            const float* __restrict__ sw,
                            const float* __restrict__ sb) {
    int t = blockIdx.x;
    int m = threadIdx.x;
    int b = t / LL, l = t % LL;
    __shared__ float xs[3][3];
    if (m < 9) {
        int c = m / 3, k = m % 3;
        int ll = l - 1 + k;
        xs[c][k] = (ll >= 0 && ll < LL) ? x[(b*3 + c)*LL + ll] : 0.f;
    }
    __syncthreads();
    float acc = sb[m];
    #pragma unroll
    for (int c = 0; c < 3; c++)
        #pragma unroll
        for (int k = 0; k < 3; k++)
            acc = fmaf(xs[c][k], sw[(m*3 + c)*3 + k], acc);
    g_h[t*DM + m] = fmaxf(acc, 0.f);
}

// ---------------- layernorm over DM=256 --------------------------------------
__global__ void ln_kernel(const float* __restrict__ in,
                          const float* __restrict__ g,
                          const float* __restrict__ b,
                          float* __restrict__ out) {
    __shared__ float sred[8];
    int t = blockIdx.x, m = threadIdx.x;
    float v = in[t*DM + m];
    float mean = block_sum_256(v, sred, m) * (1.f / DM);
    float d = v - mean;
    float var = block_sum_256(d*d, sred, m) * (1.f / DM);
    float rstd = rsqrtf(var + 1e-5f);
    out[t*DM + m] = d * rstd * g[m] + b[m];
}

// ---------------- SIMT SGEMM (small GEMMs): C = A @ W^T ----------------------
// EPI 0: C = acc ; EPI 1: C = softplus(acc + bias[n])
#define TM 128
#define TN 128
#define TK 8
template<int EPI>
__global__ __launch_bounds__(256) void sgemm_kernel(
        const float* __restrict__ A, int lda,
        const float* __restrict__ W,
        float* __restrict__ C, int ldc,
        const float* __restrict__ bias,
        int M, int N, int K) {
    __shared__ float As[TK][TM];
    __shared__ float Ws[TK][TN];
    int bm = blockIdx.y * TM;
    int bn = blockIdx.x * TN;
    int tid = threadIdx.x;
    int tr = tid / 16, tc = tid % 16;

    float acc[8][8];
    #pragma unroll
    for (int i = 0; i < 8; i++)
        #pragma unroll
        for (int j = 0; j < 8; j++) acc[i][j] = 0.f;

    for (int k0 = 0; k0 < K; k0 += TK) {
        {
            int row = tid >> 1, seg = (tid & 1) * 4;
            int gm = bm + row;
            float4 v = make_float4(0.f, 0.f, 0.f, 0.f);
            if (gm < M)
                v = *reinterpret_cast<const float4*>(A + (size_t)gm*lda + k0 + seg);
            As[seg+0][row] = v.x; As[seg+1][row] = v.y;
            As[seg+2][row] = v.z; As[seg+3][row] = v.w;
        }
        {
            int row = tid >> 1, seg = (tid & 1) * 4;
            int gn = bn + row;
            float4 v = make_float4(0.f, 0.f, 0.f, 0.f);
            if (gn < N)
                v = *reinterpret_cast<const float4*>(W + (size_t)gn*K + k0 + seg);
            Ws[seg+0][row] = v.x; Ws[seg+1][row] = v.y;
            Ws[seg+2][row] = v.z; Ws[seg+3][row] = v.w;
        }
        __syncthreads();
        #pragma unroll
        for (int kk = 0; kk < TK; kk++) {
            float a[8], bfr[8];
            *reinterpret_cast<float4*>(&a[0])   = *reinterpret_cast<float4*>(&As[kk][tr*8]);
            *reinterpret_cast<float4*>(&a[4])   = *reinterpret_cast<float4*>(&As[kk][tr*8+4]);
            *reinterpret_cast<float4*>(&bfr[0]) = *reinterpret_cast<float4*>(&Ws[kk][tc*8]);
            *reinterpret_cast<float4*>(&bfr[4]) = *reinterpret_cast<float4*>(&Ws[kk][tc*8+4]);
            #pragma unroll
            for (int i = 0; i < 8; i++)
                #pragma unroll
                for (int j = 0; j < 8; j++)
                    acc[i][j] = fmaf(a[i], bfr[j], acc[i][j]);
        }
        __syncthreads();
    }

    #pragma unroll
    for (int i = 0; i < 8; i++) {
        int gm = bm + tr*8 + i;
        if (gm >= M) continue;
        #pragma unroll
        for (int j = 0; j < 8; j++) {
            int gn = bn + tc*8 + j;
            if (gn >= N) continue;
            float v = acc[i][j];
            if (EPI == 1) v = softplusf_(v + bias[gn]);
            C[(size_t)gm*ldc + gn] = v;
        }
    }
}

// ---------------- causal depthwise conv (k=4, left pad 3) + silu -------------
__global__ void conv_silu_kernel(const float* __restrict__ cw,
                                 const float* __restrict__ cb) {
    int idx = blockIdx.x * blockDim.x + threadIdx.x;
    if (idx >= TOK*DI) return;
    int d = idx % DI;
    int t = idx / DI;
    int l = t % LL;
    float acc = cb[d];
    #pragma unroll
    for (int k = 0; k < 4; k++) {
        int ls = l - 3 + k;
        if (ls >= 0)
            acc = fmaf(g_xz[(size_t)(t - 3 + k)*(2*DI) + d], cw[d*4 + k], acc);
    }
    g_u[idx] = acc * sigmoidf_(acc);
}

// ---------------- selective scan (sequential over L) + gate ------------------
#define SCH 8
__global__ __launch_bounds__(128) void scan_kernel(const float* __restrict__ Alog,
                                                   const float* __restrict__ Dp) {
    int b = blockIdx.y;
    int d = blockIdx.x * 128 + threadIdx.x;
    int tid = threadIdx.x;

    float A[DS], h[DS];
    #pragma unroll
    for (int s = 0; s < DS; s++) {
        A[s] = -__expf(Alog[d*DS + s]);
        h[s] = 0.f;
    }
    float Dd = Dp[d];

    __shared__ float sB[SCH][DS];
    __shared__ float sC[SCH][DS];
    int t0 = b * LL;

    for (int l0 = 0; l0 < LL; l0 += SCH) {
        #pragma unroll
        for (int r = 0; r < 2; r++) {
            int i = tid + r*128;
            int step = i / (2*DS);
            int j = i % (2*DS);
            float val = g_proj[(size_t)(t0 + l0 + step)*NPROJ + DTR + j];
            if (j < DS) sB[step][j] = val;
            else        sC[step][j - DS] = val;
        }
        __syncthreads();

        float dc[SCH], uc[SCH], zc[SCH];
        #pragma unroll
        for (int i = 0; i < SCH; i++) {
            size_t t = (size_t)(t0 + l0 + i);
            dc[i] = g_delta[t*DI + d];
            uc[i] = g_u[t*DI + d];
            zc[i] = g_xz[t*2*DI + DI + d];
        }
        #pragma unroll
        for (int i = 0; i < SCH; i++) {
            float dlt = dc[i], uu = uc[i];
            float du = dlt * uu;
            float y = 0.f;
            #pragma unroll
            for (int s = 0; s < DS; s++) {
                float ep = __expf(dlt * A[s]);
                h[s] = fmaf(h[s], ep, du * sB[i][s]);
                y = fmaf(h[s], sC[i][s], y);
            }
            y = fmaf(uu, Dd, y);
            float zz = zc[i];
            y *= zz * sigmoidf_(zz);
            g_y[(size_t)(t0 + l0 + i)*DI + d] = y;
        }
        __syncthreads();
    }
}

// ---------------- final LN + head projection + sigmoid -----------------------
__global__ void head_kernel(const float* __restrict__ g,
                            const float* __restrict__ b,
                            const float* __restrict__ hw,
                            const float* __restrict__ hb,
                            float* __restrict__ out) {
    __shared__ float sred[8];
    int t = blockIdx.x, m = threadIdx.x;
    float v = g_h[t*DM + m];
    float mean = block_sum_256(v, sred, m) * (1.f / DM);
    float d = v - mean;
    float var = block_sum_256(d*d, sred, m) * (1.f / DM);
    float rstd = rsqrtf(var + 1e-5f);
    float hn = d * rstd * g[m] + b[m];
    float tot = block_sum_256(hn * hw[m], sred, m);
    if (m == 0) out[t] = sigmoidf_(tot + hb[0]);
}

// ---------------- host launcher ----------------------------------------------
extern "C" void kernel_launch(void* const* d_in, const int* in_sizes, int n_in,
                              void* d_out, int out_size) {
    const float* x       = (const float*)d_in[0];
    const float* stem_w  = (const float*)d_in[1];
    const float* stem_b  = (const float*)d_in[2];
    const float* norm_g  = (const float*)d_in[3];
    const float* norm_b  = (const float*)d_in[4];
    const float* in_w    = (const float*)d_in[5];
    const float* conv_w  = (const float*)d_in[6];
    const float* conv_b  = (const float*)d_in[7];
    const float* xpw     = (const float*)d_in[8];
    const float* dtw     = (const float*)d_in[9];
    const float* dtb     = (const float*)d_in[10];
    const float* A_log   = (const float*)d_in[11];
    const float* Dp      = (const float*)d_in[12];
    const float* out_w   = (const float*)d_in[13];
    const float* fn_g    = (const float*)d_in[14];
    const float* fn_b    = (const float*)d_in[15];
    const float* head_w  = (const float*)d_in[16];
    const float* head_b  = (const float*)d_in[17];
    float* out = (float*)d_out;

    float *p_h, *p_xn, *p_xz, *p_u, *p_proj, *p_delta, *p_y;
    cudaGetSymbolAddress((void**)&p_h,     g_h);
    cudaGetSymbolAddress((void**)&p_xn,    g_xn);
    cudaGetSymbolAddress((void**)&p_xz,    g_xz);
    cudaGetSymbolAddress((void**)&p_u,     g_u);
    cudaGetSymbolAddress((void**)&p_proj,  g_proj);
    cudaGetSymbolAddress((void**)&p_delta, g_delta);
    cudaGetSymbolAddress((void**)&p_y,     g_y);

    cudaFuncSetAttribute(mma_gemm_kernel<0>,
                         cudaFuncAttributeMaxDynamicSharedMemorySize, GEMM_SMEM);
    cudaFuncSetAttribute(mma_gemm_kernel<2>,
                         cudaFuncAttributeMaxDynamicSharedMemorySize, GEMM_SMEM);

    stem_kernel<<<TOK, 256>>>(x, stem_w, stem_b);

    for (int i = 0; i < 4; i++) {
        ln_kernel<<<TOK, 256>>>(p_h, norm_g + i*DM, norm_b + i*DM, p_xn);

        // in_proj (mma tf32): [TOK,1024] = xn[TOK,256] @ W[1024,256]^T
        {
            dim3 grid((2*DI)/GBN, TOK/GBM);
            mma_gemm_kernel<0><<<grid, 256, GEMM_SMEM>>>(
                p_xn, DM, in_w + (size_t)i*2*DI*DM, p_xz, 2*DI, DM);
        }

        conv_silu_kernel<<<(TOK*DI + 255)/256, 256>>>(conv_w + (size_t)i*DI*4,
                                                      conv_b + (size_t)i*DI);

        // x_proj (SIMT): [TOK,48] = u[TOK,512] @ xw[48,512]^T
        {
            dim3 grid((NPROJ + TN - 1)/TN, TOK/TM);
            sgemm_kernel<0><<<grid, 256>>>(p_u, DI, xpw + (size_t)i*NPROJ*DI,
                                           p_proj, NPROJ, nullptr, TOK, NPROJ, DI);
        }

        // delta (SIMT): softplus(dt[TOK,16] @ dtw[512,16]^T + dtb)
        {
            dim3 grid(DI/TN, TOK/TM);
            sgemm_kernel<1><<<grid, 256>>>(p_proj, NPROJ, dtw + (size_t)i*DI*DTR,
                                           p_delta, DI, dtb + (size_t)i*DI,
                                           TOK, DI, DTR);
        }

        // scan + gate
        {
            dim3 grid(DI/128, BN);
            scan_kernel<<<grid, 128>>>(A_log + (size_t)i*DI*DS, Dp + (size_t)i*DI);
        }

        // out proj + residual (mma tf32): h += y[TOK,512] @ ow[256,512]^T
        {
            dim3 grid(DM/GBN, TOK/GBM);
            mma_gemm_kernel<2><<<grid, 256, GEMM_SMEM>>>(
                p_y, DI, out_w + (size_t)i*DM*DI, p_h, DM, DI);
        }
    }

    head_kernel<<<TOK, 256>>>(fn_g, fn_b, head_w, head_b, out);
    (void)in_sizes; (void)n_in; (void)out_size;
}